// round 2
// baseline (speedup 1.0000x reference)
#include <cuda_runtime.h>

#define Bb 4
#define Ll 1024
#define Hh 128
#define Ee 128
#define Nn 128
#define ML (Bb*Ll)   // 4096

// ---------------- scratch (device globals: no allocations allowed) ----------------
__device__ float g_x[Bb*Ll*Ee];      // pre-conv x
__device__ float g_zs[Bb*Ll*Ee];     // silu(z)
__device__ float g_xc[Bb*Ll*Ee];     // post-conv silu(x)
__device__ float g_delta[Bb*Ll*Nn];  // softplus'd
__device__ float g_Braw[Bb*Ll*Nn];
__device__ float g_C[Bb*Ll*Hh];
__device__ float g_y[Bb*Ll*Hh];      // gated scan output (input to GEMM3)

__device__ __forceinline__ float silu_(float x){ return x / (1.f + __expf(-x)); }
__device__ __forceinline__ float softplus_(float x){ return x > 20.f ? x : log1pf(__expf(x)); }

// ---------------- generic 64x64-tile SGEMM, K=128, fused epilogues ----------------
// EPI=1: xz GEMM   (A=u,    W=W_in,  N=256) -> g_x, g_zs=silu(z)
// EPI=2: ssm GEMM  (A=g_xc, W=W_x,   N=384) -> g_delta(softplus), g_Braw, g_C
// EPI=3: out GEMM  (A=g_y,  W=W_out, N=128) -> d_out
template<int EPI>
__global__ __launch_bounds__(256) void gemm_kernel(
    const float* __restrict__ Ain, const float* __restrict__ Wp,
    const float* __restrict__ bias, float* __restrict__ Cout, int ldN)
{
    __shared__ __align__(16) float As[64][68];   // [row][k]
    __shared__ __align__(16) float Bs[64][64];   // [k][col]
    const float* Ap = (EPI == 1) ? Ain : (EPI == 2 ? g_xc : g_y);

    int tid = threadIdx.x;
    int ty = tid >> 4, tx = tid & 15;
    int row0 = blockIdx.x * 64;
    int col0 = blockIdx.y * 64;

    float acc[4][4];
    #pragma unroll
    for (int i = 0; i < 4; i++)
        #pragma unroll
        for (int j = 0; j < 4; j++) acc[i][j] = 0.f;

    #pragma unroll
    for (int kb = 0; kb < 2; ++kb) {
        // stage A: 64 rows x 64 k
        #pragma unroll
        for (int i = 0; i < 4; ++i) {
            int f = tid + i * 256;            // 0..1023 float4 slots
            int r = f >> 4, kq = f & 15;
            float4 v = *(const float4*)&Ap[(size_t)(row0 + r) * 128 + kb * 64 + kq * 4];
            *(float4*)&As[r][kq * 4] = v;
        }
        // stage B: 64 k x 64 cols
        #pragma unroll
        for (int i = 0; i < 4; ++i) {
            int f = tid + i * 256;
            int k = f >> 4, nq = f & 15;
            float4 v = *(const float4*)&Wp[(size_t)(kb * 64 + k) * ldN + col0 + nq * 4];
            *(float4*)&Bs[k][nq * 4] = v;
        }
        __syncthreads();
        #pragma unroll 16
        for (int k = 0; k < 64; ++k) {
            float4 bv = *(float4*)&Bs[k][tx * 4];
            float a0 = As[ty * 4 + 0][k];
            float a1 = As[ty * 4 + 1][k];
            float a2 = As[ty * 4 + 2][k];
            float a3 = As[ty * 4 + 3][k];
            acc[0][0] = fmaf(a0, bv.x, acc[0][0]); acc[0][1] = fmaf(a0, bv.y, acc[0][1]);
            acc[0][2] = fmaf(a0, bv.z, acc[0][2]); acc[0][3] = fmaf(a0, bv.w, acc[0][3]);
            acc[1][0] = fmaf(a1, bv.x, acc[1][0]); acc[1][1] = fmaf(a1, bv.y, acc[1][1]);
            acc[1][2] = fmaf(a1, bv.z, acc[1][2]); acc[1][3] = fmaf(a1, bv.w, acc[1][3]);
            acc[2][0] = fmaf(a2, bv.x, acc[2][0]); acc[2][1] = fmaf(a2, bv.y, acc[2][1]);
            acc[2][2] = fmaf(a2, bv.z, acc[2][2]); acc[2][3] = fmaf(a2, bv.w, acc[2][3]);
            acc[3][0] = fmaf(a3, bv.x, acc[3][0]); acc[3][1] = fmaf(a3, bv.y, acc[3][1]);
            acc[3][2] = fmaf(a3, bv.z, acc[3][2]); acc[3][3] = fmaf(a3, bv.w, acc[3][3]);
        }
        __syncthreads();
    }

    #pragma unroll
    for (int i = 0; i < 4; ++i) {
        int row = row0 + ty * 4 + i;
        #pragma unroll
        for (int j = 0; j < 4; ++j) {
            int col = col0 + tx * 4 + j;
            float v = acc[i][j] + bias[col];
            if (EPI == 1) {
                if (col < 128) g_x[(size_t)row * 128 + col] = v;
                else           g_zs[(size_t)row * 128 + col - 128] = silu_(v);
            } else if (EPI == 2) {
                if (col < 128)      g_delta[(size_t)row * 128 + col] = softplus_(v);
                else if (col < 256) g_Braw[(size_t)row * 128 + col - 128] = v;
                else                g_C[(size_t)row * 128 + col - 256] = v;
            } else {
                Cout[(size_t)row * 128 + col] = v;
            }
        }
    }
}

// ---------------- depthwise conv3 (+bias, silu) ----------------
__global__ void conv_kernel(const float* __restrict__ cw, const float* __restrict__ cb)
{
    int idx = blockIdx.x * blockDim.x + threadIdx.x;   // over B*L*E
    if (idx >= Bb * Ll * Ee) return;
    int e = idx & 127;
    int t = (idx >> 7) & (Ll - 1);
    float w0 = cw[e * 3 + 0], w1 = cw[e * 3 + 1], w2 = cw[e * 3 + 2];
    float xm = g_x[idx];
    float xl = (t > 0)      ? g_x[idx - 128] : 0.f;
    float xr = (t < Ll - 1) ? g_x[idx + 128] : 0.f;
    float v = fmaf(w0, xl, fmaf(w1, xm, fmaf(w2, xr, cb[e])));
    g_xc[idx] = silu_(v);
}

// ---------------- selective scan + fused combine ----------------
// grid (32, 4): blockIdx.x = c-group of 4, blockIdx.y = b. 256 threads = 8 warps.
// warp w: c_local = w>>1, n-half = w&1. lane covers n = nh*64 + {2ln, 2ln+1}.
__global__ __launch_bounds__(256, 1) void scan_kernel(
    const float* __restrict__ A_log, const float* __restrict__ Dv,
    const float* __restrict__ u)
{
    __shared__ __align__(16) float smd[16][128];
    __shared__ __align__(16) float smb[16][128];
    __shared__ float smx[16][4];
    __shared__ float smP[64][65];     // [n-src][tl*4 + c_local], pad=65 -> conflict-free

    int b  = blockIdx.y;
    int cg = blockIdx.x;
    int tid = threadIdx.x;
    int w = tid >> 5, ln = tid & 31;
    int cl = w >> 1, nh = w & 1;
    int c = cg * 4 + cl;

    float Ac2 = -__expf(A_log[c]) * 1.44269504f;   // A[c] * log2(e)

    const float4* del4 = (const float4*)(g_delta + (size_t)b * Ll * Nn);
    const float4* br4  = (const float4*)(g_Braw  + (size_t)b * Ll * Nn);
    const float* xcb   = g_xc + (size_t)b * Ll * Ee + cg * 4;

    float h0 = 0.f, h1 = 0.f;

    for (int t0 = 0; t0 < Ll; t0 += 16) {
        // stage 16 steps of delta and dB = delta*B (512 float4)
        #pragma unroll
        for (int i = 0; i < 2; ++i) {
            int idx = tid + i * 256;
            float4 d = del4[t0 * 32 + idx];
            float4 r = br4[t0 * 32 + idx];
            ((float4*)smd)[idx] = d;
            float4 p; p.x = d.x * r.x; p.y = d.y * r.y; p.z = d.z * r.z; p.w = d.w * r.w;
            ((float4*)smb)[idx] = p;
        }
        if (tid < 64) {
            int tl = tid >> 2, j = tid & 3;
            smx[tl][j] = xcb[(size_t)(t0 + tl) * Ee + j];
        }
        __syncthreads();

        #pragma unroll
        for (int tl = 0; tl < 16; ++tl) {
            float2 d2 = *(float2*)&smd[tl][nh * 64 + 2 * ln];
            float2 b2 = *(float2*)&smb[tl][nh * 64 + 2 * ln];
            float xv = smx[tl][cl];
            float e0, e1;
            asm("ex2.approx.ftz.f32 %0, %1;" : "=f"(e0) : "f"(d2.x * Ac2));
            asm("ex2.approx.ftz.f32 %0, %1;" : "=f"(e1) : "f"(d2.y * Ac2));
            h0 = fmaf(e0, h0, b2.x * xv);
            h1 = fmaf(e1, h1, b2.y * xv);
            smP[nh * 32 + ln][tl * 4 + cl] = h0 + h1;
        }
        __syncthreads();

        // reduce 64 n-partials per (t, c); fuse combine: y = (S*C + D*u) * silu(z)
        if (tid < 64) {
            int tl = tid >> 2, j = tid & 3;
            float s = 0.f;
            #pragma unroll
            for (int k = 0; k < 64; ++k) s += smP[k][tid];
            int t = t0 + tl;
            int cc = cg * 4 + j;
            size_t off = (size_t)b * Ll * Hh + (size_t)t * Hh + cc;
            float y = fmaf(s, g_C[off], Dv[cc] * u[off]);
            g_y[off] = y * g_zs[off];
        }
        __syncthreads();
    }
}

// ---------------- launch ----------------
extern "C" void kernel_launch(void* const* d_in, const int* in_sizes, int n_in,
                              void* d_out, int out_size)
{
    const float* u      = (const float*)d_in[0];
    const float* W_in   = (const float*)d_in[1];
    const float* b_in   = (const float*)d_in[2];
    const float* conv_w = (const float*)d_in[3];
    const float* conv_b = (const float*)d_in[4];
    const float* W_x    = (const float*)d_in[5];
    const float* b_x    = (const float*)d_in[6];
    const float* A_log  = (const float*)d_in[7];
    const float* Dv     = (const float*)d_in[8];
    const float* W_out  = (const float*)d_in[9];
    const float* b_out  = (const float*)d_in[10];
    float* out = (float*)d_out;

    dim3 blk(256);
    // 1) xz = u @ W_in + b_in ; split -> g_x, g_zs=silu(z)
    gemm_kernel<1><<<dim3(ML / 64, 256 / 64), blk>>>(u, W_in, b_in, nullptr, 256);
    // 2) depthwise conv3 + bias + silu -> g_xc
    conv_kernel<<<(Bb * Ll * Ee + 255) / 256, blk>>>(conv_w, conv_b);
    // 3) ssm = xc @ W_x + b_x ; split -> g_delta(softplus), g_Braw, g_C
    gemm_kernel<2><<<dim3(ML / 64, 384 / 64), blk>>>(nullptr, W_x, b_x, nullptr, 384);
    // 4) selective scan + combine (x C, + D*u, x silu(z)) -> g_y
    scan_kernel<<<dim3(32, Bb), blk>>>(A_log, Dv, u);
    // 5) out = g_y @ W_out + b_out
    gemm_kernel<3><<<dim3(ML / 64, 128 / 64), blk>>>(nullptr, W_out, b_out, out, 128);
}

// round 3
// speedup vs baseline: 1.2128x; 1.2128x over previous
#include <cuda_runtime.h>

#define Bb 4
#define Ll 1024
#define Hh 128
#define Ee 128
#define Nn 128
#define ML (Bb*Ll)   // 4096
#define CH 16        // number of L-chunks
#define CS 64        // chunk size (CH*CS == Ll)

// ---------------- scratch (device globals: no allocations allowed) ----------------
__device__ float g_x[Bb*Ll*Ee];      // pre-conv x
__device__ float g_zs[Bb*Ll*Ee];     // silu(z)
__device__ float g_xc[Bb*Ll*Ee];     // post-conv silu(x)
__device__ float g_delta[Bb*Ll*Nn];  // softplus'd
__device__ float g_Braw[Bb*Ll*Nn];
__device__ float g_C[Bb*Ll*Hh];
__device__ float g_y[Bb*Ll*Hh];      // gated scan output (input to GEMM3)
__device__ float g_S[Bb*Ll*Hh];      // local (then full) n-sums
__device__ float g_cumd[Bb*Ll*Nn];   // within-chunk inclusive cumsum of delta [b][t][n]
__device__ float g_hE[Bb*CH*Nn*Hh];  // chunk-end local states [b][k][n][c]
__device__ float g_h0[Bb*CH*Nn*Hh];  // chunk-start true states [b][k][n][c]

__device__ __forceinline__ float silu_(float x){ return x / (1.f + __expf(-x)); }
__device__ __forceinline__ float softplus_(float x){ return x > 20.f ? x : log1pf(__expf(x)); }
__device__ __forceinline__ float ex2f(float x){ float r; asm("ex2.approx.ftz.f32 %0, %1;" : "=f"(r) : "f"(x)); return r; }

// ---------------- generic 64x64-tile SGEMM, K=128, fused epilogues ----------------
template<int EPI>
__global__ __launch_bounds__(256) void gemm_kernel(
    const float* __restrict__ Ain, const float* __restrict__ Wp,
    const float* __restrict__ bias, float* __restrict__ Cout, int ldN)
{
    __shared__ __align__(16) float As[64][68];   // [row][k]
    __shared__ __align__(16) float Bs[64][64];   // [k][col]
    const float* Ap = (EPI == 1) ? Ain : (EPI == 2 ? g_xc : g_y);

    int tid = threadIdx.x;
    int ty = tid >> 4, tx = tid & 15;
    int row0 = blockIdx.x * 64;
    int col0 = blockIdx.y * 64;

    float acc[4][4];
    #pragma unroll
    for (int i = 0; i < 4; i++)
        #pragma unroll
        for (int j = 0; j < 4; j++) acc[i][j] = 0.f;

    #pragma unroll
    for (int kb = 0; kb < 2; ++kb) {
        #pragma unroll
        for (int i = 0; i < 4; ++i) {
            int f = tid + i * 256;
            int r = f >> 4, kq = f & 15;
            float4 v = *(const float4*)&Ap[(size_t)(row0 + r) * 128 + kb * 64 + kq * 4];
            *(float4*)&As[r][kq * 4] = v;
        }
        #pragma unroll
        for (int i = 0; i < 4; ++i) {
            int f = tid + i * 256;
            int k = f >> 4, nq = f & 15;
            float4 v = *(const float4*)&Wp[(size_t)(kb * 64 + k) * ldN + col0 + nq * 4];
            *(float4*)&Bs[k][nq * 4] = v;
        }
        __syncthreads();
        #pragma unroll 16
        for (int k = 0; k < 64; ++k) {
            float4 bv = *(float4*)&Bs[k][tx * 4];
            float a0 = As[ty * 4 + 0][k];
            float a1 = As[ty * 4 + 1][k];
            float a2 = As[ty * 4 + 2][k];
            float a3 = As[ty * 4 + 3][k];
            acc[0][0] = fmaf(a0, bv.x, acc[0][0]); acc[0][1] = fmaf(a0, bv.y, acc[0][1]);
            acc[0][2] = fmaf(a0, bv.z, acc[0][2]); acc[0][3] = fmaf(a0, bv.w, acc[0][3]);
            acc[1][0] = fmaf(a1, bv.x, acc[1][0]); acc[1][1] = fmaf(a1, bv.y, acc[1][1]);
            acc[1][2] = fmaf(a1, bv.z, acc[1][2]); acc[1][3] = fmaf(a1, bv.w, acc[1][3]);
            acc[2][0] = fmaf(a2, bv.x, acc[2][0]); acc[2][1] = fmaf(a2, bv.y, acc[2][1]);
            acc[2][2] = fmaf(a2, bv.z, acc[2][2]); acc[2][3] = fmaf(a2, bv.w, acc[2][3]);
            acc[3][0] = fmaf(a3, bv.x, acc[3][0]); acc[3][1] = fmaf(a3, bv.y, acc[3][1]);
            acc[3][2] = fmaf(a3, bv.z, acc[3][2]); acc[3][3] = fmaf(a3, bv.w, acc[3][3]);
        }
        __syncthreads();
    }

    #pragma unroll
    for (int i = 0; i < 4; ++i) {
        int row = row0 + ty * 4 + i;
        #pragma unroll
        for (int j = 0; j < 4; ++j) {
            int col = col0 + tx * 4 + j;
            float v = acc[i][j] + bias[col];
            if (EPI == 1) {
                if (col < 128) g_x[(size_t)row * 128 + col] = v;
                else           g_zs[(size_t)row * 128 + col - 128] = silu_(v);
            } else if (EPI == 2) {
                if (col < 128)      g_delta[(size_t)row * 128 + col] = softplus_(v);
                else if (col < 256) g_Braw[(size_t)row * 128 + col - 128] = v;
                else                g_C[(size_t)row * 128 + col - 256] = v;
            } else {
                Cout[(size_t)row * 128 + col] = v;
            }
        }
    }
}

// ---------------- depthwise conv3 (+bias, silu) ----------------
__global__ void conv_kernel(const float* __restrict__ cw, const float* __restrict__ cb)
{
    int idx = blockIdx.x * blockDim.x + threadIdx.x;
    if (idx >= Bb * Ll * Ee) return;
    int e = idx & 127;
    int t = (idx >> 7) & (Ll - 1);
    float w0 = cw[e * 3 + 0], w1 = cw[e * 3 + 1], w2 = cw[e * 3 + 2];
    float xm = g_x[idx];
    float xl = (t > 0)      ? g_x[idx - 128] : 0.f;
    float xr = (t < Ll - 1) ? g_x[idx + 128] : 0.f;
    float v = fmaf(w0, xl, fmaf(w1, xm, fmaf(w2, xr, cb[e])));
    g_xc[idx] = silu_(v);
}

// ---------------- Pass 1: per-chunk local scan ----------------
// grid (32, CH, Bb): blockIdx.x = c-group of 4, y = chunk, z = b. 256 threads.
// warp w: c_local = w>>1, n-half = w&1. lane covers n = nh*64 + {2ln, 2ln+1}.
// Outputs: g_S (local n-sums per t), g_hE (chunk-end local state), g_cumd (cg==0 only).
__global__ __launch_bounds__(256) void scan_local_kernel(const float* __restrict__ A_log)
{
    __shared__ __align__(16) float smd[16][128];
    __shared__ __align__(16) float smb[16][128];
    __shared__ float smx[16][4];
    __shared__ float smP[64][65];
    __shared__ float smQ[4][66];

    int b  = blockIdx.z;
    int k  = blockIdx.y;
    int cg = blockIdx.x;
    int tid = threadIdx.x;
    int w = tid >> 5, ln = tid & 31;
    int cl = w >> 1, nh = w & 1;
    int c = cg * 4 + cl;

    float Ac2 = -__expf(A_log[c]) * 1.44269504f;

    const float4* del4 = (const float4*)(g_delta + (size_t)b * Ll * Nn);
    const float4* br4  = (const float4*)(g_Braw  + (size_t)b * Ll * Nn);
    const float* xcb   = g_xc + (size_t)b * Ll * Ee + cg * 4;

    float h0 = 0.f, h1 = 0.f;
    float dc = 0.f;   // cumulative delta (threads tid<128 in cg==0 blocks)
    bool do_cum = (cg == 0) && (tid < 128);

    for (int t0 = k * CS; t0 < (k + 1) * CS; t0 += 16) {
        #pragma unroll
        for (int i = 0; i < 2; ++i) {
            int idx = tid + i * 256;
            float4 d = del4[t0 * 32 + idx];
            float4 r = br4[t0 * 32 + idx];
            ((float4*)smd)[idx] = d;
            float4 p; p.x = d.x * r.x; p.y = d.y * r.y; p.z = d.z * r.z; p.w = d.w * r.w;
            ((float4*)smb)[idx] = p;
        }
        if (tid < 64) {
            int tl = tid >> 2, j = tid & 3;
            smx[tl][j] = xcb[(size_t)(t0 + tl) * Ee + j];
        }
        __syncthreads();

        if (do_cum) {
            float* gout = g_cumd + (size_t)b * Ll * Nn + (size_t)t0 * Nn + tid;
            #pragma unroll
            for (int tl = 0; tl < 16; ++tl) { dc += smd[tl][tid]; gout[tl * 128] = dc; }
        }

        #pragma unroll
        for (int tl = 0; tl < 16; ++tl) {
            float2 d2 = *(float2*)&smd[tl][nh * 64 + 2 * ln];
            float2 b2 = *(float2*)&smb[tl][nh * 64 + 2 * ln];
            float xv = smx[tl][cl];
            float e0 = ex2f(d2.x * Ac2);
            float e1 = ex2f(d2.y * Ac2);
            h0 = fmaf(e0, h0, b2.x * xv);
            h1 = fmaf(e1, h1, b2.y * xv);
            smP[nh * 32 + ln][tl * 4 + cl] = h0 + h1;
        }
        __syncthreads();

        // distributed reduce: 64 outputs (16 t x 4 c), 64-way sums
        {
            int o = tid >> 2, q = tid & 3;
            float s = 0.f;
            #pragma unroll
            for (int j = 0; j < 16; ++j) s += smP[q * 16 + j][o];
            smQ[q][o] = s;
        }
        __syncthreads();
        if (tid < 64) {
            float s = smQ[0][tid] + smQ[1][tid] + smQ[2][tid] + smQ[3][tid];
            int tl = tid >> 2, j = tid & 3;
            g_S[(size_t)b * Ll * Hh + (size_t)(t0 + tl) * Hh + cg * 4 + j] = s;
        }
        __syncthreads();
    }

    // write chunk-end local states [b][k][n][c]
    int n0 = nh * 64 + 2 * ln;
    size_t base = ((size_t)(b * CH + k) * Nn + n0) * Hh + c;
    g_hE[base] = h0;
    g_hE[base + Hh] = h1;
}

// ---------------- Pass 2: inter-chunk state chain ----------------
// thread per (b, n, c): 16-step scan over chunks.
__global__ __launch_bounds__(256) void chain_kernel(const float* __restrict__ A_log)
{
    int g = blockIdx.x * 256 + threadIdx.x;        // 0 .. 65535
    int c = g & 127, n = (g >> 7) & 127, b = g >> 14;
    float Ac2 = -__expf(A_log[c]) * 1.44269504f;
    const float* cd = g_cumd + (size_t)b * Ll * Nn + n;
    float h = 0.f;
    #pragma unroll
    for (int k = 0; k < CH; ++k) {
        size_t idx = ((size_t)(b * CH + k) * Nn + n) * Hh + c;
        g_h0[idx] = h;
        float dec = ex2f(Ac2 * cd[(size_t)(k * CS + CS - 1) * Nn]);
        h = fmaf(dec, h, g_hE[idx]);
    }
}

// ---------------- Pass 3: fixup + combine ----------------
// grid (8, CH, Bb): 8 t-groups of T3=8 per chunk. 256 threads: c = tid&127, th = tid>>7.
// S[t,c] = S_loc + sum_n exp(A[c]*cumd[t,n]) * h0[k,n,c];  y = (S*C + D*u) * silu(z).
#define T3 8
__global__ __launch_bounds__(256) void fixup_kernel(
    const float* __restrict__ A_log, const float* __restrict__ Dv,
    const float* __restrict__ u)
{
    __shared__ __align__(16) float smh[32][128];
    __shared__ __align__(16) float smc[T3][128];

    int b = blockIdx.z, k = blockIdx.y, tg = blockIdx.x;
    int t0 = k * CS + tg * T3;
    int tid = threadIdx.x;
    int c = tid & 127, th = tid >> 7;

    float acc[4] = {0.f, 0.f, 0.f, 0.f};

    if (k > 0) {
        float Ac2 = -__expf(A_log[c]) * 1.44269504f;
        // stage cumd for the 8 t's
        #pragma unroll
        for (int i = 0; i < 4; ++i) {
            int idx = tid + i * 256;                 // 0..1023
            int tt = idx >> 7, n = idx & 127;
            smc[tt][n] = g_cumd[(size_t)b * Ll * Nn + (size_t)(t0 + tt) * Nn + n];
        }
        const float4* h0p = (const float4*)(g_h0 + ((size_t)(b * CH + k) * Nn) * Hh);
        #pragma unroll
        for (int nb = 0; nb < 4; ++nb) {
            __syncthreads();
            #pragma unroll
            for (int i = 0; i < 4; ++i) {
                int idx = tid + i * 256;             // 0..1023 float4 slots
                ((float4*)smh)[idx] = h0p[nb * 1024 + idx];
            }
            __syncthreads();
            #pragma unroll
            for (int n = 0; n < 32; ++n) {
                float hv = smh[n][c];
                #pragma unroll
                for (int j = 0; j < 4; ++j) {
                    float dl = smc[th * 4 + j][nb * 32 + n];
                    acc[j] = fmaf(ex2f(dl * Ac2), hv, acc[j]);
                }
            }
        }
    }

    #pragma unroll
    for (int j = 0; j < 4; ++j) {
        int t = t0 + th * 4 + j;
        size_t off = (size_t)b * Ll * Hh + (size_t)t * Hh + c;
        float S = g_S[off] + acc[j];
        float y = fmaf(S, g_C[off], Dv[c] * u[off]);
        g_y[off] = y * g_zs[off];
    }
}

// ---------------- launch ----------------
extern "C" void kernel_launch(void* const* d_in, const int* in_sizes, int n_in,
                              void* d_out, int out_size)
{
    const float* u      = (const float*)d_in[0];
    const float* W_in   = (const float*)d_in[1];
    const float* b_in   = (const float*)d_in[2];
    const float* conv_w = (const float*)d_in[3];
    const float* conv_b = (const float*)d_in[4];
    const float* W_x    = (const float*)d_in[5];
    const float* b_x    = (const float*)d_in[6];
    const float* A_log  = (const float*)d_in[7];
    const float* Dv     = (const float*)d_in[8];
    const float* W_out  = (const float*)d_in[9];
    const float* b_out  = (const float*)d_in[10];
    float* out = (float*)d_out;

    dim3 blk(256);
    gemm_kernel<1><<<dim3(ML / 64, 256 / 64), blk>>>(u, W_in, b_in, nullptr, 256);
    conv_kernel<<<(Bb * Ll * Ee + 255) / 256, blk>>>(conv_w, conv_b);
    gemm_kernel<2><<<dim3(ML / 64, 384 / 64), blk>>>(nullptr, W_x, b_x, nullptr, 384);
    scan_local_kernel<<<dim3(32, CH, Bb), blk>>>(A_log);
    chain_kernel<<<dim3(Bb * Nn * Hh / 256), blk>>>(A_log);
    fixup_kernel<<<dim3(CS / T3, CH, Bb), blk>>>(A_log, Dv, u);
    gemm_kernel<3><<<dim3(ML / 64, 128 / 64), blk>>>(nullptr, W_out, b_out, out, 128);
}

// round 4
// speedup vs baseline: 1.5433x; 1.2726x over previous
#include <cuda_runtime.h>

#define Bb 4
#define Ll 1024
#define Hh 128
#define Ee 128
#define Nn 128
#define ML (Bb*Ll)   // 4096
#define CH 32        // number of L-chunks
#define CS 32        // chunk size (CH*CS == Ll)

// ---------------- scratch (device globals: no allocations allowed) ----------------
__device__ float g_x[Bb*Ll*Ee];      // pre-conv x
__device__ float g_zs[Bb*Ll*Ee];     // silu(z)
__device__ float g_xc[Bb*Ll*Ee];     // post-conv silu(x)
__device__ float g_delta[Bb*Ll*Nn];  // softplus'd
__device__ float g_Braw[Bb*Ll*Nn];
__device__ float g_C[Bb*Ll*Hh];
__device__ float g_y[Bb*Ll*Hh];      // gated scan output (input to GEMM3)
__device__ float g_S[Bb*Ll*Hh];      // local (then full) n-sums
__device__ float g_cumd[Bb*Ll*Nn];   // within-chunk inclusive cumsum of delta [b][t][n]
__device__ float g_hE[Bb*CH*Nn*Hh];  // chunk-end local states [b][k][n][c]
__device__ float g_h0[Bb*CH*Nn*Hh];  // chunk-start true states [b][k][n][c]

__device__ __forceinline__ float silu_(float x){ return x / (1.f + __expf(-x)); }
__device__ __forceinline__ float softplus_(float x){ return x > 20.f ? x : log1pf(__expf(x)); }
__device__ __forceinline__ float ex2f(float x){ float r; asm("ex2.approx.ftz.f32 %0, %1;" : "=f"(r) : "f"(x)); return r; }

// ---------------- generic 64x64-tile SGEMM, K=128, fused epilogues ----------------
template<int EPI>
__global__ __launch_bounds__(256) void gemm_kernel(
    const float* __restrict__ Ain, const float* __restrict__ Wp,
    const float* __restrict__ bias, float* __restrict__ Cout, int ldN)
{
    __shared__ __align__(16) float As[64][68];   // [row][k]
    __shared__ __align__(16) float Bs[64][64];   // [k][col]
    const float* Ap = (EPI == 1) ? Ain : (EPI == 2 ? g_xc : g_y);

    int tid = threadIdx.x;
    int ty = tid >> 4, tx = tid & 15;
    int row0 = blockIdx.x * 64;
    int col0 = blockIdx.y * 64;

    float acc[4][4];
    #pragma unroll
    for (int i = 0; i < 4; i++)
        #pragma unroll
        for (int j = 0; j < 4; j++) acc[i][j] = 0.f;

    #pragma unroll
    for (int kb = 0; kb < 2; ++kb) {
        #pragma unroll
        for (int i = 0; i < 4; ++i) {
            int f = tid + i * 256;
            int r = f >> 4, kq = f & 15;
            float4 v = *(const float4*)&Ap[(size_t)(row0 + r) * 128 + kb * 64 + kq * 4];
            *(float4*)&As[r][kq * 4] = v;
        }
        #pragma unroll
        for (int i = 0; i < 4; ++i) {
            int f = tid + i * 256;
            int k = f >> 4, nq = f & 15;
            float4 v = *(const float4*)&Wp[(size_t)(kb * 64 + k) * ldN + col0 + nq * 4];
            *(float4*)&Bs[k][nq * 4] = v;
        }
        __syncthreads();
        #pragma unroll 16
        for (int k = 0; k < 64; ++k) {
            float4 bv = *(float4*)&Bs[k][tx * 4];
            float a0 = As[ty * 4 + 0][k];
            float a1 = As[ty * 4 + 1][k];
            float a2 = As[ty * 4 + 2][k];
            float a3 = As[ty * 4 + 3][k];
            acc[0][0] = fmaf(a0, bv.x, acc[0][0]); acc[0][1] = fmaf(a0, bv.y, acc[0][1]);
            acc[0][2] = fmaf(a0, bv.z, acc[0][2]); acc[0][3] = fmaf(a0, bv.w, acc[0][3]);
            acc[1][0] = fmaf(a1, bv.x, acc[1][0]); acc[1][1] = fmaf(a1, bv.y, acc[1][1]);
            acc[1][2] = fmaf(a1, bv.z, acc[1][2]); acc[1][3] = fmaf(a1, bv.w, acc[1][3]);
            acc[2][0] = fmaf(a2, bv.x, acc[2][0]); acc[2][1] = fmaf(a2, bv.y, acc[2][1]);
            acc[2][2] = fmaf(a2, bv.z, acc[2][2]); acc[2][3] = fmaf(a2, bv.w, acc[2][3]);
            acc[3][0] = fmaf(a3, bv.x, acc[3][0]); acc[3][1] = fmaf(a3, bv.y, acc[3][1]);
            acc[3][2] = fmaf(a3, bv.z, acc[3][2]); acc[3][3] = fmaf(a3, bv.w, acc[3][3]);
        }
        __syncthreads();
    }

    #pragma unroll
    for (int i = 0; i < 4; ++i) {
        int row = row0 + ty * 4 + i;
        #pragma unroll
        for (int j = 0; j < 4; ++j) {
            int col = col0 + tx * 4 + j;
            float v = acc[i][j] + bias[col];
            if (EPI == 1) {
                if (col < 128) g_x[(size_t)row * 128 + col] = v;
                else           g_zs[(size_t)row * 128 + col - 128] = silu_(v);
            } else if (EPI == 2) {
                if (col < 128)      g_delta[(size_t)row * 128 + col] = softplus_(v);
                else if (col < 256) g_Braw[(size_t)row * 128 + col - 128] = v;
                else                g_C[(size_t)row * 128 + col - 256] = v;
            } else {
                Cout[(size_t)row * 128 + col] = v;
            }
        }
    }
}

// ---------------- depthwise conv3 (+bias, silu) ----------------
__global__ void conv_kernel(const float* __restrict__ cw, const float* __restrict__ cb)
{
    int idx = blockIdx.x * blockDim.x + threadIdx.x;
    if (idx >= Bb * Ll * Ee) return;
    int e = idx & 127;
    int t = (idx >> 7) & (Ll - 1);
    float w0 = cw[e * 3 + 0], w1 = cw[e * 3 + 1], w2 = cw[e * 3 + 2];
    float xm = g_x[idx];
    float xl = (t > 0)      ? g_x[idx - 128] : 0.f;
    float xr = (t < Ll - 1) ? g_x[idx + 128] : 0.f;
    float v = fmaf(w0, xl, fmaf(w1, xm, fmaf(w2, xr, cb[e])));
    g_xc[idx] = silu_(v);
}

// ---------------- Pass 1: per-chunk local scan (4n x 4c states per thread) ----------
// grid (4, CH, Bb): blockIdx.x = c-group of 32, y = chunk, z = b. 256 threads = 8 warps.
// warp w owns c = cg*32 + w*4 + j (j=0..3); lane ln owns n = ln*4 + i (i=0..3).
__global__ __launch_bounds__(256) void scan_local_kernel(const float* __restrict__ A_log)
{
    __shared__ __align__(16) float smd[16][128];
    __shared__ __align__(16) float smb[16][128];
    __shared__ __align__(16) float smx[16][32];
    __shared__ float smP[4][32][33];    // [t%4][lane(n-grp)][c] padded row

    int b  = blockIdx.z;
    int k  = blockIdx.y;
    int cg = blockIdx.x;
    int tid = threadIdx.x;
    int w = tid >> 5, ln = tid & 31;

    float Ac2[4];
    #pragma unroll
    for (int j = 0; j < 4; ++j)
        Ac2[j] = -__expf(A_log[cg * 32 + w * 4 + j]) * 1.44269504f;

    const float4* del4 = (const float4*)(g_delta + (size_t)b * Ll * Nn);
    const float4* br4  = (const float4*)(g_Braw  + (size_t)b * Ll * Nn);
    const float* xcb   = g_xc + (size_t)b * Ll * Ee + cg * 32;

    float h[4][4];
    #pragma unroll
    for (int j = 0; j < 4; ++j)
        #pragma unroll
        for (int i = 0; i < 4; ++i) h[j][i] = 0.f;

    float dc = 0.f;
    bool do_cum = (cg == 0) && (tid < 128);

    for (int t0 = k * CS; t0 < (k + 1) * CS; t0 += 16) {
        // stage delta and dB = delta*B for 16 t (512 float4)
        #pragma unroll
        for (int i = 0; i < 2; ++i) {
            int idx = tid + i * 256;
            float4 d = del4[t0 * 32 + idx];
            float4 r = br4[t0 * 32 + idx];
            ((float4*)smd)[idx] = d;
            float4 p; p.x = d.x * r.x; p.y = d.y * r.y; p.z = d.z * r.z; p.w = d.w * r.w;
            ((float4*)smb)[idx] = p;
        }
        // stage x for 16 t x 32 c
        if (tid < 128) {
            int tt = tid >> 3, q = tid & 7;
            *(float4*)&smx[tt][q * 4] = *(const float4*)&xcb[(size_t)(t0 + tt) * Ee + q * 4];
        }
        __syncthreads();

        if (do_cum) {
            float* gout = g_cumd + (size_t)b * Ll * Nn + (size_t)t0 * Nn + tid;
            #pragma unroll
            for (int tl = 0; tl < 16; ++tl) { dc += smd[tl][tid]; gout[tl * 128] = dc; }
        }

        #pragma unroll
        for (int tb = 0; tb < 16; tb += 4) {
            #pragma unroll
            for (int tt = 0; tt < 4; ++tt) {
                int t = tb + tt;
                float4 d4 = *(float4*)&smd[t][ln * 4];
                float4 b4 = *(float4*)&smb[t][ln * 4];
                float4 x4 = *(float4*)&smx[t][w * 4];
                float dn[4] = {d4.x, d4.y, d4.z, d4.w};
                float bn[4] = {b4.x, b4.y, b4.z, b4.w};
                float xs[4] = {x4.x, x4.y, x4.z, x4.w};
                #pragma unroll
                for (int j = 0; j < 4; ++j) {
                    #pragma unroll
                    for (int i = 0; i < 4; ++i) {
                        float e = ex2f(dn[i] * Ac2[j]);
                        h[j][i] = fmaf(e, h[j][i], bn[i] * xs[j]);
                    }
                    smP[tt][ln][w * 4 + j] = (h[j][0] + h[j][1]) + (h[j][2] + h[j][3]);
                }
            }
            __syncthreads();
            if (tid < 128) {
                int tt = tid >> 5, c = tid & 31;
                float s = 0.f;
                #pragma unroll
                for (int q = 0; q < 32; ++q) s += smP[tt][q][c];
                int t = t0 + tb + tt;
                g_S[(size_t)b * Ll * Hh + (size_t)t * Hh + cg * 32 + c] = s;
            }
            __syncthreads();
        }
    }

    // chunk-end local states [b][k][n][c]
    size_t base = ((size_t)(b * CH + k) * Nn + ln * 4) * Hh + cg * 32 + w * 4;
    #pragma unroll
    for (int i = 0; i < 4; ++i) {
        float4 v; v.x = h[0][i]; v.y = h[1][i]; v.z = h[2][i]; v.w = h[3][i];
        *(float4*)&g_hE[base + (size_t)i * Hh] = v;
    }
}

// ---------------- Pass 2: inter-chunk state chain ----------------
__global__ __launch_bounds__(256) void chain_kernel(const float* __restrict__ A_log)
{
    int g = blockIdx.x * 256 + threadIdx.x;        // 0 .. 65535
    int c = g & 127, n = (g >> 7) & 127, b = g >> 14;
    float Ac2 = -__expf(A_log[c]) * 1.44269504f;
    const float* cd = g_cumd + (size_t)b * Ll * Nn + n;
    float h = 0.f;
    #pragma unroll
    for (int k = 0; k < CH; ++k) {
        size_t idx = ((size_t)(b * CH + k) * Nn + n) * Hh + c;
        g_h0[idx] = h;
        float dec = ex2f(Ac2 * cd[(size_t)(k * CS + CS - 1) * Nn]);
        h = fmaf(dec, h, g_hE[idx]);
    }
}

// ---------------- Pass 3: fixup + combine ----------------
// grid (CS/T3, CH, Bb). 256 threads: c = tid&127, th = tid>>7.
#define T3 8
__global__ __launch_bounds__(256) void fixup_kernel(
    const float* __restrict__ A_log, const float* __restrict__ Dv,
    const float* __restrict__ u)
{
    __shared__ __align__(16) float smh[32][128];
    __shared__ __align__(16) float smc[T3][128];

    int b = blockIdx.z, k = blockIdx.y, tg = blockIdx.x;
    int t0 = k * CS + tg * T3;
    int tid = threadIdx.x;
    int c = tid & 127, th = tid >> 7;

    float acc[4] = {0.f, 0.f, 0.f, 0.f};

    if (k > 0) {
        float Ac2 = -__expf(A_log[c]) * 1.44269504f;
        #pragma unroll
        for (int i = 0; i < 4; ++i) {
            int idx = tid + i * 256;
            int tt = idx >> 7, n = idx & 127;
            smc[tt][n] = g_cumd[(size_t)b * Ll * Nn + (size_t)(t0 + tt) * Nn + n];
        }
        const float4* h0p = (const float4*)(g_h0 + ((size_t)(b * CH + k) * Nn) * Hh);
        #pragma unroll
        for (int nb = 0; nb < 4; ++nb) {
            __syncthreads();
            #pragma unroll
            for (int i = 0; i < 4; ++i) {
                int idx = tid + i * 256;
                ((float4*)smh)[idx] = h0p[nb * 1024 + idx];
            }
            __syncthreads();
            #pragma unroll
            for (int n = 0; n < 32; ++n) {
                float hv = smh[n][c];
                #pragma unroll
                for (int j = 0; j < 4; ++j) {
                    float dl = smc[th * 4 + j][nb * 32 + n];
                    acc[j] = fmaf(ex2f(dl * Ac2), hv, acc[j]);
                }
            }
        }
    }

    #pragma unroll
    for (int j = 0; j < 4; ++j) {
        int t = t0 + th * 4 + j;
        size_t off = (size_t)b * Ll * Hh + (size_t)t * Hh + c;
        float S = g_S[off] + acc[j];
        float y = fmaf(S, g_C[off], Dv[c] * u[off]);
        g_y[off] = y * g_zs[off];
    }
}

// ---------------- launch ----------------
extern "C" void kernel_launch(void* const* d_in, const int* in_sizes, int n_in,
                              void* d_out, int out_size)
{
    const float* u      = (const float*)d_in[0];
    const float* W_in   = (const float*)d_in[1];
    const float* b_in   = (const float*)d_in[2];
    const float* conv_w = (const float*)d_in[3];
    const float* conv_b = (const float*)d_in[4];
    const float* W_x    = (const float*)d_in[5];
    const float* b_x    = (const float*)d_in[6];
    const float* A_log  = (const float*)d_in[7];
    const float* Dv     = (const float*)d_in[8];
    const float* W_out  = (const float*)d_in[9];
    const float* b_out  = (const float*)d_in[10];
    float* out = (float*)d_out;

    dim3 blk(256);
    gemm_kernel<1><<<dim3(ML / 64, 256 / 64), blk>>>(u, W_in, b_in, nullptr, 256);
    conv_kernel<<<(Bb * Ll * Ee + 255) / 256, blk>>>(conv_w, conv_b);
    gemm_kernel<2><<<dim3(ML / 64, 384 / 64), blk>>>(nullptr, W_x, b_x, nullptr, 384);
    scan_local_kernel<<<dim3(4, CH, Bb), blk>>>(A_log);
    chain_kernel<<<dim3(Bb * Nn * Hh / 256), blk>>>(A_log);
    fixup_kernel<<<dim3(CS / T3, CH, Bb), blk>>>(A_log, Dv, u);
    gemm_kernel<3><<<dim3(ML / 64, 128 / 64), blk>>>(nullptr, W_out, b_out, out, 128);
}